// round 8
// baseline (speedup 1.0000x reference)
#include <cuda_runtime.h>
#include <math.h>

#define BSZ 4096
#define HSZ 512
#define KSZ 32
#define DSZ 20
#define NPAIR 496   // 32*31/2
#define NBB 64
#define GRID 256
#define TPB 256

typedef unsigned long long u64;

// ---------------- device scratch (no allocations allowed) ----------------
__device__ float  g_pm[NBB][HSZ][KSZ];   // partial class sums  [bb][h][k]
__device__ float  g_ps[NBB][HSZ][KSZ];   // partial sum h^2c^2  [bb][h][k]
__device__ double g_pcnt[NBB][KSZ];
__device__ float  g_m[KSZ][HSZ];
__device__ float  g_w[KSZ][HSZ];
__device__ float  g_inv[4096];           // 1/j reciprocal table

struct PairMeta { float ci, cj, bf, thresh; double bd, lbeta; int nu, odd; };
__device__ PairMeta g_meta[NPAIR];

__device__ unsigned long long g_acc;     // fixed-point (2^-32) accumulator
__device__ unsigned int g_done;

__device__ unsigned int g_bar_count = 0;
__device__ volatile unsigned int g_bar_gen = 0;

__device__ __forceinline__ void grid_barrier() {
    __syncthreads();
    __threadfence();
    if (threadIdx.x == 0) {
        unsigned int gen = g_bar_gen;
        unsigned int t = atomicAdd(&g_bar_count, 1u);
        if (t == GRID - 1) {
            g_bar_count = 0u;
            __threadfence();
            g_bar_gen = gen + 1u;
        } else {
            while (g_bar_gen == gen) __nanosleep(64);
        }
    }
    __syncthreads();
    __threadfence();
}

__device__ __forceinline__ u64 ffma2(u64 a, u64 b, u64 c) {
    u64 d;
    asm("fma.rn.f32x2 %0, %1, %2, %3;" : "=l"(d) : "l"(a), "l"(b), "l"(c));
    return d;
}
__device__ __forceinline__ float f2lo(u64 v) { return __uint_as_float((unsigned)v); }
__device__ __forceinline__ float f2hi(u64 v) { return __uint_as_float((unsigned)(v >> 32)); }

union F4U { float4 f; u64 d[2]; };

// ln B(1/2, b): ratio Gamma(b+1/2)/Gamma(b) via shift recurrence + asymptotic.
__device__ __forceinline__ double lbeta_half(double b) {
    double z = b, prod = 1.0;
#pragma unroll 1
    while (z < 32.0) { prod *= z / (z + 0.5); z += 1.0; }
    double iz = 1.0 / z;
    double ser = 1.0 + iz * (-0.125 + iz * (0.0078125 +
                 iz * (0.0048828125 + iz * (-0.000640869140625))));
    return 0.57236494292470008707 - log(prod * sqrt(z) * ser);
}

// Lentz CF fallback (non-integer nu only), warp-uniform, f32-safe tolerance.
__device__ __forceinline__ float betacf_warp(float a, float b, float x) {
    const float FPMIN = 1e-30f;
    float qab = a + b, qap = a + 1.0f, qam = a - 1.0f;
    float c = 1.0f;
    float d = 1.0f - qab * x / qap;
    if (fabsf(d) < FPMIN) d = FPMIN;
    d = 1.0f / d;
    float hh = d;
    bool done = false;
#pragma unroll 1
    for (int m = 1; m <= 200; m++) {
        if (!done) {
            float fm = (float)m, m2 = 2.0f * fm;
            float aa = fm * (b - fm) * x / ((qam + m2) * (a + m2));
            d = 1.0f + aa * d; if (fabsf(d) < FPMIN) d = FPMIN;
            c = 1.0f + aa / c; if (fabsf(c) < FPMIN) c = FPMIN;
            d = 1.0f / d;
            hh *= d * c;
            aa = -(a + fm) * (qab + fm) * x / ((a + m2) * (qap + m2));
            d = 1.0f + aa * d; if (fabsf(d) < FPMIN) d = FPMIN;
            c = 1.0f + aa / c; if (fabsf(c) < FPMIN) c = FPMIN;
            d = 1.0f / d;
            float del = d * c;
            hh *= del;
            if (fabsf(del - 1.0f) < 2.4e-7f) done = true;
        }
        if (__all_sync(0xffffffffu, done)) break;
    }
    return hh;
}

__device__ __forceinline__ void pair_ij(int p, int& ii, int& jj) {
    int i = 0, rem = p;
    while (rem >= (KSZ - 1 - i)) { rem -= (KSZ - 1 - i); i++; }
    ii = i; jj = i + 1 + rem;
}

// ================== K1: stats (phase 1 only, barrier-free) =================
// grid: (NBB, 4) -> bb = blockIdx.x, hb = blockIdx.y
__global__ __launch_bounds__(TPB) void stats_kernel(const float* __restrict__ hidden,
                                                    const float* __restrict__ cluster) {
    __shared__ float sh_hidp[32][256];   // packed pairs {h, h^2}
    __shared__ float sh_cp[32][64];      // packed pairs {c, c^2}
    __shared__ double sh_cnt[TPB];

    const int tid = (int)threadIdx.x;
    const int bb = (int)blockIdx.x;      // 0..63
    const int hb = (int)blockIdx.y;      // 0..3   (FIX: was blockIdx.x >> 6)
    const int h0 = hb * 128;
    const int b0 = bb * 64;
    const int hg = tid >> 3;             // owns 4 h
    const int kg = tid & 7;              // owns 4 k

    if (bb == 0 && hb == 0 && tid == 0) { g_acc = 0ULL; g_done = 0u; }

    u64 acc[4][4];
#pragma unroll
    for (int i = 0; i < 4; i++)
#pragma unroll
        for (int j = 0; j < 4; j++) acc[i][j] = 0ULL;

    for (int bt = 0; bt < 64; bt += 32) {
        __syncthreads();
#pragma unroll
        for (int it = 0; it < 4; it++) {
            int e = tid + it * 256;
            int r = e >> 5, c4 = e & 31;
            float4 v = *(const float4*)&hidden[(b0 + bt + r) * HSZ + h0 + c4 * 4];
            float4 w0 = make_float4(v.x, v.x * v.x, v.y, v.y * v.y);
            float4 w1 = make_float4(v.z, v.z * v.z, v.w, v.w * v.w);
            *(float4*)&sh_hidp[r][c4 * 8] = w0;
            *(float4*)&sh_hidp[r][c4 * 8 + 4] = w1;
        }
        {
            int r = tid >> 3, c4 = tid & 7;
            float4 v = *(const float4*)&cluster[(b0 + bt + r) * KSZ + c4 * 4];
            float4 w0 = make_float4(v.x, v.x * v.x, v.y, v.y * v.y);
            float4 w1 = make_float4(v.z, v.z * v.z, v.w, v.w * v.w);
            *(float4*)&sh_cp[r][c4 * 8] = w0;
            *(float4*)&sh_cp[r][c4 * 8 + 4] = w1;
        }
        __syncthreads();
#pragma unroll 4
        for (int r = 0; r < 32; r++) {
            F4U qh0, qh1, qc0, qc1;
            qh0.f = *(const float4*)&sh_hidp[r][hg * 8];
            qh1.f = *(const float4*)&sh_hidp[r][hg * 8 + 4];
            qc0.f = *(const float4*)&sh_cp[r][kg * 8];
            qc1.f = *(const float4*)&sh_cp[r][kg * 8 + 4];
            u64 hp[4] = { qh0.d[0], qh0.d[1], qh1.d[0], qh1.d[1] };
            u64 cpk[4] = { qc0.d[0], qc0.d[1], qc1.d[0], qc1.d[1] };
#pragma unroll
            for (int i = 0; i < 4; i++)
#pragma unroll
                for (int j = 0; j < 4; j++)
                    acc[i][j] = ffma2(hp[i], cpk[j], acc[i][j]);
        }
    }
#pragma unroll
    for (int i = 0; i < 4; i++) {
        int h = h0 + hg * 4 + i;
        float4 pm4 = make_float4(f2lo(acc[i][0]), f2lo(acc[i][1]), f2lo(acc[i][2]), f2lo(acc[i][3]));
        float4 ps4 = make_float4(f2hi(acc[i][0]), f2hi(acc[i][1]), f2hi(acc[i][2]), f2hi(acc[i][3]));
        *(float4*)&g_pm[bb][h][kg * 4] = pm4;
        *(float4*)&g_ps[bb][h][kg * 4] = ps4;
    }

    if (hb == 0) {
        const int k = tid & 31;
        const int seg = tid >> 5;
        double s = 0.0;
#pragma unroll
        for (int r = seg; r < 64; r += 8)
            s += (double)cluster[(b0 + r) * KSZ + k];
        __syncthreads();
        sh_cnt[tid] = s;
        __syncthreads();
        if (tid < 128) sh_cnt[tid] += sh_cnt[tid + 128];
        __syncthreads();
        if (tid < 64) sh_cnt[tid] += sh_cnt[tid + 64];
        __syncthreads();
        if (tid < 32) g_pcnt[bb][tid] = sh_cnt[tid] + sh_cnt[tid + 32];
    }
}

// ============ K2: reduce + meta, grid barrier, pairs + finish ==============
__global__ __launch_bounds__(TPB, 2) void pairs_kernel(float* __restrict__ out) {
    __shared__ float sx[2][320];

    const int tid = (int)threadIdx.x;
    const int lane = tid & 31, warp = tid >> 5;

    // ----- Phase 2: reduce -> m,w ; pair meta ; reciprocal table -----
    {
        int gt = (int)blockIdx.x * TPB + tid;
        if (gt < 2 * KSZ * HSZ) {              // blocks 0..127
            int cell = gt >> 1;
            int half = gt & 1;
            int k = cell & 31;
            int h = cell >> 5;
            float smm = 0.f, ss = 0.f;
            int p0 = half * 32;
#pragma unroll 8
            for (int p = p0; p < p0 + 32; p++) {
                smm += g_pm[p][h][k];
                ss  += g_ps[p][h][k];
            }
            float smo = __shfl_xor_sync(0xffffffffu, smm, 1);
            float sso = __shfl_xor_sync(0xffffffffu, ss, 1);
            if (half == 0) {
                float M = smm + smo;
                float S2 = ss + sso;
                g_m[k][h] = M;
                g_w[k][h] = S2 + (float)(BSZ - 2) * M * M;
            }
        } else if (gt < 2 * KSZ * HSZ + 4096) { // blocks 128..143: 1/j table
            int idx = gt - 2 * KSZ * HSZ;
            g_inv[idx] = (idx > 0) ? (1.0f / (float)idx) : 0.0f;
        }
        if (warp < 2 && lane == 0) {
            int p = (int)blockIdx.x + warp * GRID;
            if (p < NPAIR) {
                int ii, jj; pair_ij(p, ii, jj);
                double si = 0.0, sj = 0.0;
#pragma unroll 8
                for (int q = 0; q < NBB; q++) { si += g_pcnt[q][ii]; sj += g_pcnt[q][jj]; }
                float ci = (float)rint(si), cj = (float)rint(sj);
                float d2 = (ci + cj) - 2.0f;
                if (d2 == 0.0f) d2 += 1e-5f;
                double bd = 0.5 * (double)d2;
                PairMeta mt;
                mt.ci = ci; mt.cj = cj;
                mt.bf = (float)bd;
                mt.thresh = 1.5f / ((float)bd + 2.5f);
                mt.bd = bd;
                bool isint = (d2 == rintf(d2)) && (d2 >= 1.0f) && (d2 <= 4094.0f);
                mt.nu = isint ? (int)d2 : 0;
                mt.odd = ((int)d2) & 1;
                mt.lbeta = isint ? 0.0 : lbeta_half(bd);
                g_meta[p] = mt;
            }
        }
    }

    grid_barrier();

    // ----- Phase 3: pairs (x, top-20, betainc) + fixed-point finish -----
    {
        const int npair_here = ((int)blockIdx.x + GRID < NPAIR) ? 2 : 1;

        for (int q = 0; q < npair_here; q++) {
            int p = (int)blockIdx.x + q * GRID;
            int ii, jj; pair_ij(p, ii, jj);
            float ci = g_meta[p].ci, cj = g_meta[p].cj;
#pragma unroll
            for (int half = 0; half < 2; half++) {
                int h = tid + half * 256;
                float mi = g_m[ii][h], mj = g_m[jj][h];
                float wi = g_w[ii][h], wj = g_w[jj][h];
                float gmv = 0.5f * (mi + mj);
                float di = mi - gmv, dj = mj - gmv;
                float between = di * di * ci + dj * dj * cj;
                float x = between / (between + wi + wj);
                x = fminf(fmaxf(x, 1e-37f), 1.0f - 1e-5f);
                float v = x;
#pragma unroll
                for (int kk = 2; kk <= 32; kk <<= 1)
#pragma unroll
                    for (int jjs = kk >> 1; jjs > 0; jjs >>= 1) {
                        float o = __shfl_xor_sync(0xffffffffu, v, jjs);
                        bool up = ((lane & kk) == 0);
                        bool lo = ((lane & jjs) == 0);
                        v = (up == lo) ? fmaxf(v, o) : fminf(v, o);
                    }
                if (lane < 20) sx[q][warp * 40 + half * 20 + lane] = v;
            }
        }
        __syncthreads();

        if (warp < npair_here) {
            int p = (int)blockIdx.x + warp * GRID;
            PairMeta mt = g_meta[p];

            float r[10];
#pragma unroll
            for (int q = 0; q < 10; q++) r[q] = sx[warp][lane * 10 + q];
#pragma unroll
            for (int a = 0; a < 10; a++)
#pragma unroll
                for (int bq = 0; bq < 9 - a; bq++) {
                    float x0 = r[bq], x1 = r[bq + 1];
                    r[bq] = fmaxf(x0, x1); r[bq + 1] = fminf(x0, x1);
                }
            int ptr = 0;
            float head = r[0];
            float myx = 0.5f;
#pragma unroll 1
            for (int t = 0; t < DSZ; t++) {
                float mx = head;
#pragma unroll
                for (int off = 16; off; off >>= 1)
                    mx = fmaxf(mx, __shfl_xor_sync(0xffffffffu, mx, off));
                int wl = (head == mx) ? lane : 32;
#pragma unroll
                for (int off = 16; off; off >>= 1)
                    wl = min(wl, __shfl_xor_sync(0xffffffffu, wl, off));
                if (lane == wl) {
                    ptr++;
                    float nh = -1e38f;
#pragma unroll
                    for (int q = 1; q < 10; q++) nh = (ptr == q) ? r[q] : nh;
                    head = nh;
                }
                if (lane == t) myx = mx;
            }

            // I_x(1/2, nu/2): exact finite Student-t series
            double logI;
            float xx = myx;
            float uu = 1.0f - xx;
            if (mt.nu > 0) {
                if (mt.odd) {
                    int n = (mt.nu - 1) >> 1;
                    float D = 0.0f;
                    if (n > 0) {
                        float term = 1.0f; D = 1.0f;
#pragma unroll 1
                        for (int j = 1; j < n; j++) {
                            float f = 1.0f - g_inv[2 * j + 1];
                            term *= uu * f;
                            D += term;
                        }
                    }
                    float s = sqrtf(xx), su = sqrtf(uu);
                    float A = 0.63661977236758134f * (asinf(s) + s * su * D);
                    logI = (double)logf(fminf(A, 1.0f));
                } else {
                    int n = mt.nu >> 1;
                    float term = 1.0f, S = 1.0f;
#pragma unroll 1
                    for (int j = 1; j < n; j++) {
                        float f = fmaf(-0.5f, g_inv[j], 1.0f);
                        term *= uu * f;
                        S += term;
                    }
                    logI = (double)logf(fminf(sqrtf(xx) * S, 1.0f));
                }
            } else {
                bool sel = xx < mt.thresh;
                float pa = sel ? 0.5f : mt.bf;
                float pb = sel ? mt.bf : 0.5f;
                float px = sel ? xx : uu;
                float cf = betacf_warp(pa, pb, px);
                double lbt = 0.5 * (double)logf(xx) + mt.bd * (double)log1pf(-xx) - mt.lbeta;
                if (sel) {
                    logI = lbt + (double)logf(2.0f * cf);
                } else {
                    double T = exp(lbt + (double)logf(cf / mt.bf));
                    logI = (double)log1pf(-(float)T);
                }
            }

            double contrib = (lane < DSZ) ? logI : 0.0;
#pragma unroll
            for (int off = 16; off; off >>= 1)
                contrib += __shfl_xor_sync(0xffffffffu, contrib, off);

            if (lane == 0) {
                long long fx = __double2ll_rn(contrib * 4294967296.0);
                atomicAdd(&g_acc, (unsigned long long)fx);
                __threadfence();
                unsigned int t = atomicAdd(&g_done, 1u);
                if (t == NPAIR - 1) {
                    long long total = (long long)atomicAdd(&g_acc, 0ULL);
                    out[0] = (float)(-(double)total * (1.0 / 4294967296.0));
                }
            }
        }
    }
}

extern "C" void kernel_launch(void* const* d_in, const int* in_sizes, int n_in,
                              void* d_out, int out_size) {
    (void)in_sizes; (void)n_in; (void)out_size;
    const float* hidden  = (const float*)d_in[0];
    const float* cluster = (const float*)d_in[1];
    float* out = (float*)d_out;

    dim3 gA(NBB, 4);
    stats_kernel<<<gA, TPB>>>(hidden, cluster);
    pairs_kernel<<<GRID, TPB>>>(out);
}